// round 11
// baseline (speedup 1.0000x reference)
#include <cuda_runtime.h>

// ---------------------------------------------------------------------------
// STN forward: conv1(3->8)+relu+pool -> conv2(8->10)+relu+pool -> fc1(31360->32)
//              +relu -> fc2(32->6)=theta -> affine grid + bilinear sample.
// All fp32. Convs: packed fma.rn.f32x2, weights in __constant__.
// R11: sampler restructured to 1 thread / (pixel,channel): per-warp loads and
// stores touch ~1 L1 line each (3x fewer wavefronts than per-pixel version).
// ---------------------------------------------------------------------------

typedef unsigned long long u64;

__device__ __forceinline__ u64 pack2(float v) {
    u64 r; asm("mov.b64 %0, {%1, %1};" : "=l"(r) : "f"(v)); return r;
}
__device__ __forceinline__ void unpack2(u64 v, float& lo, float& hi) {
    asm("mov.b64 {%0, %1}, %2;" : "=f"(lo), "=f"(hi) : "l"(v));
}
__device__ __forceinline__ void ffma2(u64& acc, u64 a, u64 b) {
    asm("fma.rn.f32x2 %0, %1, %2, %0;" : "+l"(acc) : "l"(a), "l"(b));
}

// ------------------------------- weights in constant -----------------------
__constant__ __align__(16) float c_w1[216];   // (3,3,3,8) HWIO
__constant__ __align__(16) float c_b1[8];
__constant__ __align__(16) float c_w2[720];   // (3,3,8,10)
__constant__ __align__(16) float c_b2[10];

// ------------------------------- scratch ----------------------------------
__device__ __align__(16) float g_p1[128 * 112 * 112 * 8];   // pooled conv1 out
__device__ __align__(16) float g_p2[128 * 56 * 56 * 10];    // pooled conv2 out
__device__ float g_part2[8 * 128 * 32];                     // fc1 k-split partials

// ---------------------------------------------------------------------------
// conv1 + relu + 2x2 maxpool.  Block = 256 thr -> 16x16 pooled tile.
// ---------------------------------------------------------------------------
__global__ void __launch_bounds__(256, 4)
k_conv1(const float* __restrict__ x) {
    __shared__ float s[34 * 108];

    const int tid = threadIdx.x;
    const int b   = blockIdx.z;
    const int by0 = blockIdx.y * 16, bx0 = blockIdx.x * 16;
    const int gy0 = by0 * 2 - 1;
    const int gxf = (bx0 * 2 - 2) * 3;
    const float* xb = x + (size_t)b * (224 * 224 * 3);

    {
        int i  = tid;
        int r  = tid / 54;
        int c2 = tid - r * 54;
#pragma unroll
        for (int it = 0; it < 8; ++it) {
            if (i < 1836) {
                int y    = gy0 + r;
                int fcol = gxf + 2 * c2;
                float2 v = make_float2(0.f, 0.f);
                if ((unsigned)y < 224u && (unsigned)fcol < 672u)
                    v = *(const float2*)(xb + y * 672 + fcol);
                *(float2*)(s + r * 108 + 2 * c2) = v;
            }
            i += 256; r += 4; c2 += 40;
            if (c2 >= 54) { c2 -= 54; r += 1; }
        }
    }
    __syncthreads();

    const int px = tid & 15, py = tid >> 4;
    const u64* cw = (const u64*)c_w1;
    const u64* cb = (const u64*)c_b1;

    u64 acc[2][2][4];
#pragma unroll
    for (int p = 0; p < 4; p++) {
        u64 bp = cb[p];
        acc[0][0][p] = bp; acc[0][1][p] = bp; acc[1][0][p] = bp; acc[1][1][p] = bp;
    }

    const float* tb = s + (2 * py) * 108 + (1 + 2 * px) * 3;

#pragma unroll
    for (int ci = 0; ci < 3; ci++) {
        u64 pv[4][4];
#pragma unroll
        for (int r = 0; r < 4; r++)
#pragma unroll
            for (int k = 0; k < 4; k++)
                pv[r][k] = pack2(tb[r * 108 + k * 3 + ci]);
#pragma unroll
        for (int ky = 0; ky < 3; ky++)
#pragma unroll
        for (int kx = 0; kx < 3; kx++) {
            const int wo = (((ky * 3 + kx) * 3 + ci) * 8) >> 1;
            u64 w0 = cw[wo + 0], w1 = cw[wo + 1], w2 = cw[wo + 2], w3 = cw[wo + 3];
#pragma unroll
            for (int dy = 0; dy < 2; dy++)
#pragma unroll
            for (int dx = 0; dx < 2; dx++) {
                u64 vv = pv[dy + ky][dx + kx];
                ffma2(acc[dy][dx][0], vv, w0);
                ffma2(acc[dy][dx][1], vv, w1);
                ffma2(acc[dy][dx][2], vv, w2);
                ffma2(acc[dy][dx][3], vv, w3);
            }
        }
    }

    float o[8];
#pragma unroll
    for (int p = 0; p < 4; p++) {
        float a0, a1, b0f, b1f, c0, c1, d0, d1;
        unpack2(acc[0][0][p], a0, a1);
        unpack2(acc[0][1][p], b0f, b1f);
        unpack2(acc[1][0][p], c0, c1);
        unpack2(acc[1][1][p], d0, d1);
        o[2 * p]     = fmaxf(fmaxf(fmaxf(a0, b0f), fmaxf(c0, d0)), 0.f);
        o[2 * p + 1] = fmaxf(fmaxf(fmaxf(a1, b1f), fmaxf(c1, d1)), 0.f);
    }
    float* dst = g_p1 + (((size_t)b * 112 + by0 + py) * 112 + (bx0 + px)) * 8;
    *(float4*)dst       = make_float4(o[0], o[1], o[2], o[3]);
    *((float4*)dst + 1) = make_float4(o[4], o[5], o[6], o[7]);
}

// ---------------------------------------------------------------------------
// conv2 + relu + 2x2 maxpool.  Block = 224 thr -> 28x8 pooled tile.
// ---------------------------------------------------------------------------
__global__ void __launch_bounds__(224, 2)
k_conv2() {
    __shared__ float s[8 * 1084];

    const int tid = threadIdx.x;
    const int b   = blockIdx.z;
    const int by0 = blockIdx.y * 8, bx0 = blockIdx.x * 28;
    const int gy0 = by0 * 2 - 1, gx0 = bx0 * 2 - 1;
    const float* pb = g_p1 + (size_t)b * (112 * 112 * 8);

    {
        int i  = tid;
        int r  = tid / 116;
        int c2 = tid - r * 116;
#pragma unroll
        for (int it = 0; it < 10; ++it) {
            if (i < 2088) {
                int col = c2 >> 1, half = c2 & 1;
                int y = gy0 + r, xc = gx0 + col;
                float4 v = make_float4(0.f, 0.f, 0.f, 0.f);
                if ((unsigned)y < 112u && (unsigned)xc < 112u)
                    v = *(const float4*)(pb + ((size_t)(y * 112 + xc)) * 8 + half * 4);
                int base = r * 60 + col;
                int c0 = half * 4;
                s[(c0 + 0) * 1084 + base] = v.x;
                s[(c0 + 1) * 1084 + base] = v.y;
                s[(c0 + 2) * 1084 + base] = v.z;
                s[(c0 + 3) * 1084 + base] = v.w;
            }
            i += 224; r += 1; c2 += 108;
            if (c2 >= 116) { c2 -= 116; r += 1; }
        }
    }
    __syncthreads();

    const int py = tid / 28, px = tid - py * 28;
    const u64* cw = (const u64*)c_w2;
    const u64* cb = (const u64*)c_b2;

    u64 acc[2][2][5];
#pragma unroll
    for (int p = 0; p < 5; p++) {
        u64 bp = cb[p];
        acc[0][0][p] = bp; acc[0][1][p] = bp; acc[1][0][p] = bp; acc[1][1][p] = bp;
    }

#pragma unroll
    for (int ci = 0; ci < 8; ci++) {
        const float* sp = s + ci * 1084 + (2 * py) * 60 + 2 * px;
        u64 pv[4][4];
#pragma unroll
        for (int r = 0; r < 4; r++) {
            float2 a = *(const float2*)(sp + r * 60);
            float2 c = *(const float2*)(sp + r * 60 + 2);
            pv[r][0] = pack2(a.x); pv[r][1] = pack2(a.y);
            pv[r][2] = pack2(c.x); pv[r][3] = pack2(c.y);
        }
#pragma unroll
        for (int ky = 0; ky < 3; ky++)
#pragma unroll
        for (int kx = 0; kx < 3; kx++) {
            const int wo = (((ky * 3 + kx) * 8 + ci) * 10) >> 1;
            u64 w0 = cw[wo + 0], w1 = cw[wo + 1], w2 = cw[wo + 2],
                w3 = cw[wo + 3], w4 = cw[wo + 4];
#pragma unroll
            for (int dy = 0; dy < 2; dy++)
#pragma unroll
            for (int dx = 0; dx < 2; dx++) {
                u64 vv = pv[dy + ky][dx + kx];
                ffma2(acc[dy][dx][0], vv, w0);
                ffma2(acc[dy][dx][1], vv, w1);
                ffma2(acc[dy][dx][2], vv, w2);
                ffma2(acc[dy][dx][3], vv, w3);
                ffma2(acc[dy][dx][4], vv, w4);
            }
        }
    }

    float o[10];
#pragma unroll
    for (int p = 0; p < 5; p++) {
        float a0, a1, b0f, b1f, c0, c1, d0, d1;
        unpack2(acc[0][0][p], a0, a1);
        unpack2(acc[0][1][p], b0f, b1f);
        unpack2(acc[1][0][p], c0, c1);
        unpack2(acc[1][1][p], d0, d1);
        o[2 * p]     = fmaxf(fmaxf(fmaxf(a0, b0f), fmaxf(c0, d0)), 0.f);
        o[2 * p + 1] = fmaxf(fmaxf(fmaxf(a1, b1f), fmaxf(c1, d1)), 0.f);
    }
    float* dst = g_p2 + (((size_t)b * 56 + by0 + py) * 56 + (bx0 + px)) * 10;
#pragma unroll
    for (int p = 0; p < 5; p++)
        *(float2*)(dst + 2 * p) = make_float2(o[2 * p], o[2 * p + 1]);
}

// ---------------------------------------------------------------------------
// fc1 partials: grid (8 k-splits, 32 batch-groups), 256 thr. 4 batches/block.
// ---------------------------------------------------------------------------
__global__ void __launch_bounds__(256)
k_fc1(const float* __restrict__ w) {
    __shared__ float sred[8 * 128];
    const int ks = blockIdx.x, bg = blockIdx.y;
    const int tid = threadIdx.x;
    const int jh = tid & 1;
    const int kl = tid >> 1;

    float acc[4][16];
#pragma unroll
    for (int bb = 0; bb < 4; bb++)
#pragma unroll
        for (int j = 0; j < 16; j++) acc[bb][j] = 0.f;

    const float* p0 = g_p2 + (size_t)(bg * 4 + 0) * 31360;
    const float* p1 = p0 + 31360;
    const float* p2 = p0 + 2 * 31360;
    const float* p3 = p0 + 3 * 31360;
    const int kend = ks * 3920 + 3920;

    for (int k = ks * 3920 + kl; k < kend; k += 128) {
        const float* wr = w + (size_t)k * 32 + jh * 16;
        float4 wa = *(const float4*)(wr);
        float4 wb = *(const float4*)(wr + 4);
        float4 wc = *(const float4*)(wr + 8);
        float4 wd = *(const float4*)(wr + 12);
        float wv[16] = {wa.x, wa.y, wa.z, wa.w, wb.x, wb.y, wb.z, wb.w,
                        wc.x, wc.y, wc.z, wc.w, wd.x, wd.y, wd.z, wd.w};
        float vs[4] = {p0[k], p1[k], p2[k], p3[k]};
#pragma unroll
        for (int bb = 0; bb < 4; bb++)
#pragma unroll
            for (int j = 0; j < 16; j++)
                acc[bb][j] = fmaf(vs[bb], wv[j], acc[bb][j]);
    }

#pragma unroll
    for (int off = 16; off >= 2; off >>= 1)
#pragma unroll
        for (int bb = 0; bb < 4; bb++)
#pragma unroll
            for (int j = 0; j < 16; j++)
                acc[bb][j] += __shfl_down_sync(0xffffffffu, acc[bb][j], off);

    const int lane = tid & 31, wp = tid >> 5;
    if (lane < 2) {
        float* d = &sred[wp * 128 + lane * 64];
#pragma unroll
        for (int bb = 0; bb < 4; bb++)
#pragma unroll
            for (int j = 0; j < 16; j++) d[bb * 16 + j] = acc[bb][j];
    }
    __syncthreads();
    if (tid < 128) {
        float sum = 0.f;
#pragma unroll
        for (int wp2 = 0; wp2 < 8; wp2++) sum += sred[wp2 * 128 + tid];
        int jh2 = tid >> 6, bb = (tid >> 4) & 3, jj = tid & 15;
        g_part2[ks * 4096 + (bg * 4 + bb) * 32 + jh2 * 16 + jj] = sum;
    }
}

// ---------------------------------------------------------------------------
// FUSED sampler: theta recompute + affine grid + bilinear sampling.
// Block = 768 thr over 256 pixels: phase1 (256 thr) computes per-pixel
// coords/weights into smem; phase2 (768 thr) handles one (pixel,channel)
// output float each -> per-warp loads/stores touch ~1 L1 line.
// ---------------------------------------------------------------------------
__global__ void __launch_bounds__(768, 2)
k_sample(const float* __restrict__ x,
         const float* __restrict__ fc1b, const float* __restrict__ fc2w,
         const float* __restrict__ fc2b, float* __restrict__ out) {
    __shared__ float ts[32];
    __shared__ float th[6];
    __shared__ int   sxy[256];
    __shared__ float swa[256], swb[256], swc[256], swd[256];

    const int b   = blockIdx.y;
    const int tid = threadIdx.x;

    // theta recompute (warp 0)
    if (tid < 32) {
        float sum = fc1b[tid];
#pragma unroll
        for (int ks = 0; ks < 8; ks++) sum += g_part2[ks * 4096 + b * 32 + tid];
        ts[tid] = fmaxf(sum, 0.f);
    }
    __syncthreads();
    if (tid < 6) {
        float t = fc2b[tid];
#pragma unroll
        for (int jj = 0; jj < 32; jj++) t = fmaf(ts[jj], fc2w[jj * 6 + tid], t);
        th[tid] = t;
    }
    __syncthreads();

    // phase 1: per-pixel coords + weights
    if (tid < 256) {
        const int pix = blockIdx.x * 256 + tid;
        const int yy = pix / 224;
        const int xx = pix - yy * 224;
        float xt = fmaf((float)xx, 2.f / 223.f, -1.f);
        float yt = fmaf((float)yy, 2.f / 223.f, -1.f);
        float gx = fmaf(th[0], xt, fmaf(th[1], yt, th[2]));
        float gy = fmaf(th[3], xt, fmaf(th[4], yt, th[5]));
        float xs = (gx + 1.f) * 111.5f;
        float ys = (gy + 1.f) * 111.5f;

        int x0 = min(max((int)floorf(xs), 0), 223);
        int y0 = min(max((int)floorf(ys), 0), 223);
        float x1f = (float)min(x0 + 1, 223);
        float y1f = (float)min(y0 + 1, 223);
        float x0f = (float)x0, y0f = (float)y0;
        swa[tid] = (x1f - xs) * (y1f - ys);
        swb[tid] = (x1f - xs) * (ys - y0f);
        swc[tid] = (xs - x0f) * (y1f - ys);
        swd[tid] = (xs - x0f) * (ys - y0f);
        sxy[tid] = x0 | (y0 << 16);
    }
    __syncthreads();

    // phase 2: one output float per thread
    {
        const int p = tid / 3;               // local pixel 0..255
        const int c = tid - 3 * p;           // channel 0..2
        const int xy = sxy[p];
        const int x0 = xy & 0xffff, y0 = xy >> 16;
        const int x1 = min(x0 + 1, 223), y1 = min(y0 + 1, 223);

        const float* xb = x + (size_t)b * 150528;
        const int r0 = y0 * 672, r1 = y1 * 672;
        const int c0 = x0 * 3 + c, c1 = x1 * 3 + c;

        float i00 = xb[r0 + c0];
        float i01 = xb[r1 + c0];
        float i10 = xb[r0 + c1];
        float i11 = xb[r1 + c1];

        float v = swa[p] * i00 + swb[p] * i01 + swc[p] * i10 + swd[p] * i11;
        out[(size_t)b * 150528 + blockIdx.x * 768 + tid] = v;
    }
}

// ---------------------------------------------------------------------------
extern "C" void kernel_launch(void* const* d_in, const int* in_sizes, int n_in,
                              void* d_out, int out_size) {
    const float* x   = (const float*)d_in[0];
    const float* c1w = (const float*)d_in[1];
    const float* c1b = (const float*)d_in[2];
    const float* c2w = (const float*)d_in[3];
    const float* c2b = (const float*)d_in[4];
    const float* f1w = (const float*)d_in[5];
    const float* f1b = (const float*)d_in[6];
    const float* f2w = (const float*)d_in[7];
    const float* f2b = (const float*)d_in[8];
    float* out = (float*)d_out;

    cudaMemcpyToSymbolAsync(c_w1, c1w, 216 * sizeof(float), 0,
                            cudaMemcpyDeviceToDevice, 0);
    cudaMemcpyToSymbolAsync(c_b1, c1b, 8 * sizeof(float), 0,
                            cudaMemcpyDeviceToDevice, 0);
    cudaMemcpyToSymbolAsync(c_w2, c2w, 720 * sizeof(float), 0,
                            cudaMemcpyDeviceToDevice, 0);
    cudaMemcpyToSymbolAsync(c_b2, c2b, 10 * sizeof(float), 0,
                            cudaMemcpyDeviceToDevice, 0);

    k_conv1 <<<dim3(7, 7, 128), 256>>> (x);
    k_conv2 <<<dim3(2, 7, 128), 224>>> ();
    k_fc1   <<<dim3(8, 32),     256>>> (f1w);
    // 4th kernel launch (ncu slot): fused theta + restructured sampler
    k_sample<<<dim3(196, 128),  768>>> (x, f1b, f2w, f2b, out);
}

// round 12
// speedup vs baseline: 1.2738x; 1.2738x over previous
#include <cuda_runtime.h>

// ---------------------------------------------------------------------------
// STN forward: conv1(3->8)+relu+pool -> conv2(8->10)+relu+pool -> fc1(31360->32)
//              +relu -> fc2(32->6)=theta -> affine grid + bilinear sample.
// All fp32. Convs: packed fma.rn.f32x2, weights in __constant__ (R8-proven).
// R12: sampler = per-pixel threads + block-level smem staging of the source
// bounding box (coalesced region load, LDS sampling), gmem fallback for
// oversize boxes. Theta recompute fused into the sampler.
// ---------------------------------------------------------------------------

typedef unsigned long long u64;

__device__ __forceinline__ u64 pack2(float v) {
    u64 r; asm("mov.b64 %0, {%1, %1};" : "=l"(r) : "f"(v)); return r;
}
__device__ __forceinline__ void unpack2(u64 v, float& lo, float& hi) {
    asm("mov.b64 {%0, %1}, %2;" : "=f"(lo), "=f"(hi) : "l"(v));
}
__device__ __forceinline__ void ffma2(u64& acc, u64 a, u64 b) {
    asm("fma.rn.f32x2 %0, %1, %2, %0;" : "+l"(acc) : "l"(a), "l"(b));
}

// ------------------------------- weights in constant -----------------------
__constant__ __align__(16) float c_w1[216];   // (3,3,3,8) HWIO
__constant__ __align__(16) float c_b1[8];
__constant__ __align__(16) float c_w2[720];   // (3,3,8,10)
__constant__ __align__(16) float c_b2[10];

// ------------------------------- scratch ----------------------------------
__device__ __align__(16) float g_p1[128 * 112 * 112 * 8];   // pooled conv1 out
__device__ __align__(16) float g_p2[128 * 56 * 56 * 10];    // pooled conv2 out
__device__ float g_part2[8 * 128 * 32];                     // fc1 k-split partials

// ---------------------------------------------------------------------------
// conv1 + relu + 2x2 maxpool.  Block = 256 thr -> 16x16 pooled tile.
// ---------------------------------------------------------------------------
__global__ void __launch_bounds__(256, 4)
k_conv1(const float* __restrict__ x) {
    __shared__ float s[34 * 108];

    const int tid = threadIdx.x;
    const int b   = blockIdx.z;
    const int by0 = blockIdx.y * 16, bx0 = blockIdx.x * 16;
    const int gy0 = by0 * 2 - 1;
    const int gxf = (bx0 * 2 - 2) * 3;
    const float* xb = x + (size_t)b * (224 * 224 * 3);

    {
        int i  = tid;
        int r  = tid / 54;
        int c2 = tid - r * 54;
#pragma unroll
        for (int it = 0; it < 8; ++it) {
            if (i < 1836) {
                int y    = gy0 + r;
                int fcol = gxf + 2 * c2;
                float2 v = make_float2(0.f, 0.f);
                if ((unsigned)y < 224u && (unsigned)fcol < 672u)
                    v = *(const float2*)(xb + y * 672 + fcol);
                *(float2*)(s + r * 108 + 2 * c2) = v;
            }
            i += 256; r += 4; c2 += 40;
            if (c2 >= 54) { c2 -= 54; r += 1; }
        }
    }
    __syncthreads();

    const int px = tid & 15, py = tid >> 4;
    const u64* cw = (const u64*)c_w1;
    const u64* cb = (const u64*)c_b1;

    u64 acc[2][2][4];
#pragma unroll
    for (int p = 0; p < 4; p++) {
        u64 bp = cb[p];
        acc[0][0][p] = bp; acc[0][1][p] = bp; acc[1][0][p] = bp; acc[1][1][p] = bp;
    }

    const float* tb = s + (2 * py) * 108 + (1 + 2 * px) * 3;

#pragma unroll
    for (int ci = 0; ci < 3; ci++) {
        u64 pv[4][4];
#pragma unroll
        for (int r = 0; r < 4; r++)
#pragma unroll
            for (int k = 0; k < 4; k++)
                pv[r][k] = pack2(tb[r * 108 + k * 3 + ci]);
#pragma unroll
        for (int ky = 0; ky < 3; ky++)
#pragma unroll
        for (int kx = 0; kx < 3; kx++) {
            const int wo = (((ky * 3 + kx) * 3 + ci) * 8) >> 1;
            u64 w0 = cw[wo + 0], w1 = cw[wo + 1], w2 = cw[wo + 2], w3 = cw[wo + 3];
#pragma unroll
            for (int dy = 0; dy < 2; dy++)
#pragma unroll
            for (int dx = 0; dx < 2; dx++) {
                u64 vv = pv[dy + ky][dx + kx];
                ffma2(acc[dy][dx][0], vv, w0);
                ffma2(acc[dy][dx][1], vv, w1);
                ffma2(acc[dy][dx][2], vv, w2);
                ffma2(acc[dy][dx][3], vv, w3);
            }
        }
    }

    float o[8];
#pragma unroll
    for (int p = 0; p < 4; p++) {
        float a0, a1, b0f, b1f, c0, c1, d0, d1;
        unpack2(acc[0][0][p], a0, a1);
        unpack2(acc[0][1][p], b0f, b1f);
        unpack2(acc[1][0][p], c0, c1);
        unpack2(acc[1][1][p], d0, d1);
        o[2 * p]     = fmaxf(fmaxf(fmaxf(a0, b0f), fmaxf(c0, d0)), 0.f);
        o[2 * p + 1] = fmaxf(fmaxf(fmaxf(a1, b1f), fmaxf(c1, d1)), 0.f);
    }
    float* dst = g_p1 + (((size_t)b * 112 + by0 + py) * 112 + (bx0 + px)) * 8;
    *(float4*)dst       = make_float4(o[0], o[1], o[2], o[3]);
    *((float4*)dst + 1) = make_float4(o[4], o[5], o[6], o[7]);
}

// ---------------------------------------------------------------------------
// conv2 + relu + 2x2 maxpool.  Block = 224 thr -> 28x8 pooled tile.
// ---------------------------------------------------------------------------
__global__ void __launch_bounds__(224, 2)
k_conv2() {
    __shared__ float s[8 * 1084];

    const int tid = threadIdx.x;
    const int b   = blockIdx.z;
    const int by0 = blockIdx.y * 8, bx0 = blockIdx.x * 28;
    const int gy0 = by0 * 2 - 1, gx0 = bx0 * 2 - 1;
    const float* pb = g_p1 + (size_t)b * (112 * 112 * 8);

    {
        int i  = tid;
        int r  = tid / 116;
        int c2 = tid - r * 116;
#pragma unroll
        for (int it = 0; it < 10; ++it) {
            if (i < 2088) {
                int col = c2 >> 1, half = c2 & 1;
                int y = gy0 + r, xc = gx0 + col;
                float4 v = make_float4(0.f, 0.f, 0.f, 0.f);
                if ((unsigned)y < 112u && (unsigned)xc < 112u)
                    v = *(const float4*)(pb + ((size_t)(y * 112 + xc)) * 8 + half * 4);
                int base = r * 60 + col;
                int c0 = half * 4;
                s[(c0 + 0) * 1084 + base] = v.x;
                s[(c0 + 1) * 1084 + base] = v.y;
                s[(c0 + 2) * 1084 + base] = v.z;
                s[(c0 + 3) * 1084 + base] = v.w;
            }
            i += 224; r += 1; c2 += 108;
            if (c2 >= 116) { c2 -= 116; r += 1; }
        }
    }
    __syncthreads();

    const int py = tid / 28, px = tid - py * 28;
    const u64* cw = (const u64*)c_w2;
    const u64* cb = (const u64*)c_b2;

    u64 acc[2][2][5];
#pragma unroll
    for (int p = 0; p < 5; p++) {
        u64 bp = cb[p];
        acc[0][0][p] = bp; acc[0][1][p] = bp; acc[1][0][p] = bp; acc[1][1][p] = bp;
    }

#pragma unroll
    for (int ci = 0; ci < 8; ci++) {
        const float* sp = s + ci * 1084 + (2 * py) * 60 + 2 * px;
        u64 pv[4][4];
#pragma unroll
        for (int r = 0; r < 4; r++) {
            float2 a = *(const float2*)(sp + r * 60);
            float2 c = *(const float2*)(sp + r * 60 + 2);
            pv[r][0] = pack2(a.x); pv[r][1] = pack2(a.y);
            pv[r][2] = pack2(c.x); pv[r][3] = pack2(c.y);
        }
#pragma unroll
        for (int ky = 0; ky < 3; ky++)
#pragma unroll
        for (int kx = 0; kx < 3; kx++) {
            const int wo = (((ky * 3 + kx) * 8 + ci) * 10) >> 1;
            u64 w0 = cw[wo + 0], w1 = cw[wo + 1], w2 = cw[wo + 2],
                w3 = cw[wo + 3], w4 = cw[wo + 4];
#pragma unroll
            for (int dy = 0; dy < 2; dy++)
#pragma unroll
            for (int dx = 0; dx < 2; dx++) {
                u64 vv = pv[dy + ky][dx + kx];
                ffma2(acc[dy][dx][0], vv, w0);
                ffma2(acc[dy][dx][1], vv, w1);
                ffma2(acc[dy][dx][2], vv, w2);
                ffma2(acc[dy][dx][3], vv, w3);
                ffma2(acc[dy][dx][4], vv, w4);
            }
        }
    }

    float o[10];
#pragma unroll
    for (int p = 0; p < 5; p++) {
        float a0, a1, b0f, b1f, c0, c1, d0, d1;
        unpack2(acc[0][0][p], a0, a1);
        unpack2(acc[0][1][p], b0f, b1f);
        unpack2(acc[1][0][p], c0, c1);
        unpack2(acc[1][1][p], d0, d1);
        o[2 * p]     = fmaxf(fmaxf(fmaxf(a0, b0f), fmaxf(c0, d0)), 0.f);
        o[2 * p + 1] = fmaxf(fmaxf(fmaxf(a1, b1f), fmaxf(c1, d1)), 0.f);
    }
    float* dst = g_p2 + (((size_t)b * 56 + by0 + py) * 56 + (bx0 + px)) * 10;
#pragma unroll
    for (int p = 0; p < 5; p++)
        *(float2*)(dst + 2 * p) = make_float2(o[2 * p], o[2 * p + 1]);
}

// ---------------------------------------------------------------------------
// fc1 partials: grid (8 k-splits, 32 batch-groups), 256 thr. 4 batches/block.
// ---------------------------------------------------------------------------
__global__ void __launch_bounds__(256)
k_fc1(const float* __restrict__ w) {
    __shared__ float sred[8 * 128];
    const int ks = blockIdx.x, bg = blockIdx.y;
    const int tid = threadIdx.x;
    const int jh = tid & 1;
    const int kl = tid >> 1;

    float acc[4][16];
#pragma unroll
    for (int bb = 0; bb < 4; bb++)
#pragma unroll
        for (int j = 0; j < 16; j++) acc[bb][j] = 0.f;

    const float* p0 = g_p2 + (size_t)(bg * 4 + 0) * 31360;
    const float* p1 = p0 + 31360;
    const float* p2 = p0 + 2 * 31360;
    const float* p3 = p0 + 3 * 31360;
    const int kend = ks * 3920 + 3920;

    for (int k = ks * 3920 + kl; k < kend; k += 128) {
        const float* wr = w + (size_t)k * 32 + jh * 16;
        float4 wa = *(const float4*)(wr);
        float4 wb = *(const float4*)(wr + 4);
        float4 wc = *(const float4*)(wr + 8);
        float4 wd = *(const float4*)(wr + 12);
        float wv[16] = {wa.x, wa.y, wa.z, wa.w, wb.x, wb.y, wb.z, wb.w,
                        wc.x, wc.y, wc.z, wc.w, wd.x, wd.y, wd.z, wd.w};
        float vs[4] = {p0[k], p1[k], p2[k], p3[k]};
#pragma unroll
        for (int bb = 0; bb < 4; bb++)
#pragma unroll
            for (int j = 0; j < 16; j++)
                acc[bb][j] = fmaf(vs[bb], wv[j], acc[bb][j]);
    }

#pragma unroll
    for (int off = 16; off >= 2; off >>= 1)
#pragma unroll
        for (int bb = 0; bb < 4; bb++)
#pragma unroll
            for (int j = 0; j < 16; j++)
                acc[bb][j] += __shfl_down_sync(0xffffffffu, acc[bb][j], off);

    const int lane = tid & 31, wp = tid >> 5;
    if (lane < 2) {
        float* d = &sred[wp * 128 + lane * 64];
#pragma unroll
        for (int bb = 0; bb < 4; bb++)
#pragma unroll
            for (int j = 0; j < 16; j++) d[bb * 16 + j] = acc[bb][j];
    }
    __syncthreads();
    if (tid < 128) {
        float sum = 0.f;
#pragma unroll
        for (int wp2 = 0; wp2 < 8; wp2++) sum += sred[wp2 * 128 + tid];
        int jh2 = tid >> 6, bb = (tid >> 4) & 3, jj = tid & 15;
        g_part2[ks * 4096 + (bg * 4 + bb) * 32 + jh2 * 16 + jj] = sum;
    }
}

// ---------------------------------------------------------------------------
// FUSED sampler: theta recompute + affine grid + bilinear sampling with
// block-level smem staging. 256 thr = 256 pixels. The block's source
// bounding box (rows x cols) is loaded coalesced into smem when it fits
// (<=4 rows x <=872 floats -- always true for near-identity theta); else
// per-thread gmem fallback (correct for arbitrary theta).
// ---------------------------------------------------------------------------
#define SROWS 4
#define SCOLS 872

__global__ void __launch_bounds__(256)
k_sample(const float* __restrict__ x,
         const float* __restrict__ fc1b, const float* __restrict__ fc2w,
         const float* __restrict__ fc2b, float* __restrict__ out) {
    __shared__ float ts[32];
    __shared__ float th[6];
    __shared__ float region[SROWS * SCOLS];
    __shared__ int   rmnx[8], rmxx[8], rmny[8], rmxy[8];

    const int b   = blockIdx.y;
    const int tid = threadIdx.x;

    // ---- theta recompute (warp 0) ----
    if (tid < 32) {
        float sum = fc1b[tid];
#pragma unroll
        for (int ks = 0; ks < 8; ks++) sum += g_part2[ks * 4096 + b * 32 + tid];
        ts[tid] = fmaxf(sum, 0.f);
    }
    __syncthreads();
    if (tid < 6) {
        float t = fc2b[tid];
#pragma unroll
        for (int jj = 0; jj < 32; jj++) t = fmaf(ts[jj], fc2w[jj * 6 + tid], t);
        th[tid] = t;
    }
    __syncthreads();

    // ---- per-pixel coords + weights (registers) ----
    const int pix = blockIdx.x * 256 + tid;           // 196*256 = 50176 exact
    const int yy = pix / 224;
    const int xx = pix - yy * 224;
    float xt = fmaf((float)xx, 2.f / 223.f, -1.f);
    float yt = fmaf((float)yy, 2.f / 223.f, -1.f);
    float gx = fmaf(th[0], xt, fmaf(th[1], yt, th[2]));
    float gy = fmaf(th[3], xt, fmaf(th[4], yt, th[5]));
    float xs = (gx + 1.f) * 111.5f;
    float ys = (gy + 1.f) * 111.5f;

    int x0 = min(max((int)floorf(xs), 0), 223);
    int y0 = min(max((int)floorf(ys), 0), 223);
    int x1 = min(x0 + 1, 223);
    int y1 = min(y0 + 1, 223);
    float x0f = (float)x0, x1f = (float)x1, y0f = (float)y0, y1f = (float)y1;
    float wa = (x1f - xs) * (y1f - ys);
    float wb = (x1f - xs) * (ys - y0f);
    float wc = (xs - x0f) * (y1f - ys);
    float wd = (xs - x0f) * (ys - y0f);

    // ---- block bounding box (warp shuffles + smem combine) ----
    int mnx = x0, mxx = x1, mny = y0, mxy = y1;
#pragma unroll
    for (int off = 16; off >= 1; off >>= 1) {
        mnx = min(mnx, __shfl_xor_sync(0xffffffffu, mnx, off));
        mxx = max(mxx, __shfl_xor_sync(0xffffffffu, mxx, off));
        mny = min(mny, __shfl_xor_sync(0xffffffffu, mny, off));
        mxy = max(mxy, __shfl_xor_sync(0xffffffffu, mxy, off));
    }
    const int wp = tid >> 5;
    if ((tid & 31) == 0) { rmnx[wp] = mnx; rmxx[wp] = mxx; rmny[wp] = mny; rmxy[wp] = mxy; }
    __syncthreads();
    mnx = rmnx[0]; mxx = rmxx[0]; mny = rmny[0]; mxy = rmxy[0];
#pragma unroll
    for (int i = 1; i < 8; i++) {
        mnx = min(mnx, rmnx[i]); mxx = max(mxx, rmxx[i]);
        mny = min(mny, rmny[i]); mxy = max(mxy, rmxy[i]);
    }
    const int rows   = mxy - mny + 1;
    const int cols_f = (mxx - mnx + 1) * 3;
    const float* xb  = x + (size_t)b * 150528;

    float i00, i01, i10, i11;
    float j00, j01, j10, j11;
    float k00, k01, k10, k11;

    if (rows <= SROWS && cols_f <= SCOLS) {
        // staged path: coalesced region load, then LDS sampling
        const int gbase = mny * 672 + mnx * 3;
        for (int r = 0; r < rows; ++r) {
            const float* src = xb + gbase + r * 672;
            float* dst = region + r * SCOLS;
            for (int i = tid; i < cols_f; i += 256) dst[i] = src[i];
        }
        __syncthreads();
        const int b0 = (y0 - mny) * SCOLS + (x0 - mnx) * 3;
        const int b1 = (y1 - mny) * SCOLS + (x0 - mnx) * 3;
        const int dxo = (x1 - x0) * 3;
        i00 = region[b0];     i01 = region[b1];     i10 = region[b0 + dxo];     i11 = region[b1 + dxo];
        j00 = region[b0 + 1]; j01 = region[b1 + 1]; j10 = region[b0 + dxo + 1]; j11 = region[b1 + dxo + 1];
        k00 = region[b0 + 2]; k01 = region[b1 + 2]; k10 = region[b0 + dxo + 2]; k11 = region[b1 + dxo + 2];
    } else {
        // fallback: direct gmem loads (arbitrary theta)
        const int r0 = y0 * 672, r1 = y1 * 672;
        const int c0 = x0 * 3, c1 = x1 * 3;
        i00 = xb[r0 + c0];     i01 = xb[r1 + c0];     i10 = xb[r0 + c1];     i11 = xb[r1 + c1];
        j00 = xb[r0 + c0 + 1]; j01 = xb[r1 + c0 + 1]; j10 = xb[r0 + c1 + 1]; j11 = xb[r1 + c1 + 1];
        k00 = xb[r0 + c0 + 2]; k01 = xb[r1 + c0 + 2]; k10 = xb[r0 + c1 + 2]; k11 = xb[r1 + c1 + 2];
    }

    float* o = out + (size_t)b * 150528 + pix * 3;
    o[0] = wa * i00 + wb * i01 + wc * i10 + wd * i11;
    o[1] = wa * j00 + wb * j01 + wc * j10 + wd * j11;
    o[2] = wa * k00 + wb * k01 + wc * k10 + wd * k11;
}

// ---------------------------------------------------------------------------
extern "C" void kernel_launch(void* const* d_in, const int* in_sizes, int n_in,
                              void* d_out, int out_size) {
    const float* x   = (const float*)d_in[0];
    const float* c1w = (const float*)d_in[1];
    const float* c1b = (const float*)d_in[2];
    const float* c2w = (const float*)d_in[3];
    const float* c2b = (const float*)d_in[4];
    const float* f1w = (const float*)d_in[5];
    const float* f1b = (const float*)d_in[6];
    const float* f2w = (const float*)d_in[7];
    const float* f2b = (const float*)d_in[8];
    float* out = (float*)d_out;

    cudaMemcpyToSymbolAsync(c_w1, c1w, 216 * sizeof(float), 0,
                            cudaMemcpyDeviceToDevice, 0);
    cudaMemcpyToSymbolAsync(c_b1, c1b, 8 * sizeof(float), 0,
                            cudaMemcpyDeviceToDevice, 0);
    cudaMemcpyToSymbolAsync(c_w2, c2w, 720 * sizeof(float), 0,
                            cudaMemcpyDeviceToDevice, 0);
    cudaMemcpyToSymbolAsync(c_b2, c2b, 10 * sizeof(float), 0,
                            cudaMemcpyDeviceToDevice, 0);

    k_conv1 <<<dim3(7, 7, 128), 256>>> (x);
    k_conv2 <<<dim3(2, 7, 128), 224>>> ();
    k_fc1   <<<dim3(8, 32),     256>>> (f1w);
    // 4th kernel launch (ncu slot): fused theta + staged sampler
    k_sample<<<dim3(196, 128),  256>>> (x, f1b, f2w, f2b, out);
}

// round 13
// speedup vs baseline: 1.6036x; 1.2589x over previous
#include <cuda_runtime.h>

// ---------------------------------------------------------------------------
// STN forward: conv1(3->8)+relu+pool -> conv2(8->10)+relu+pool -> fc1(31360->32)
//              +relu -> fc2(32->6)=theta -> affine grid + bilinear sample.
// All fp32. Convs: packed fma.rn.f32x2, weights in __constant__ (R8-proven).
// R13: sampler = R10 per-pixel structure with 2 pixels/thread (MLP 12 -> 24)
// + fused theta recompute. Single lever vs R10.
// ---------------------------------------------------------------------------

typedef unsigned long long u64;

__device__ __forceinline__ u64 pack2(float v) {
    u64 r; asm("mov.b64 %0, {%1, %1};" : "=l"(r) : "f"(v)); return r;
}
__device__ __forceinline__ void unpack2(u64 v, float& lo, float& hi) {
    asm("mov.b64 {%0, %1}, %2;" : "=f"(lo), "=f"(hi) : "l"(v));
}
__device__ __forceinline__ void ffma2(u64& acc, u64 a, u64 b) {
    asm("fma.rn.f32x2 %0, %1, %2, %0;" : "+l"(acc) : "l"(a), "l"(b));
}

// ------------------------------- weights in constant -----------------------
__constant__ __align__(16) float c_w1[216];   // (3,3,3,8) HWIO
__constant__ __align__(16) float c_b1[8];
__constant__ __align__(16) float c_w2[720];   // (3,3,8,10)
__constant__ __align__(16) float c_b2[10];

// ------------------------------- scratch ----------------------------------
__device__ __align__(16) float g_p1[128 * 112 * 112 * 8];   // pooled conv1 out
__device__ __align__(16) float g_p2[128 * 56 * 56 * 10];    // pooled conv2 out
__device__ float g_part2[8 * 128 * 32];                     // fc1 k-split partials

// ---------------------------------------------------------------------------
// conv1 + relu + 2x2 maxpool.  Block = 256 thr -> 16x16 pooled tile.
// ---------------------------------------------------------------------------
__global__ void __launch_bounds__(256, 4)
k_conv1(const float* __restrict__ x) {
    __shared__ float s[34 * 108];

    const int tid = threadIdx.x;
    const int b   = blockIdx.z;
    const int by0 = blockIdx.y * 16, bx0 = blockIdx.x * 16;
    const int gy0 = by0 * 2 - 1;
    const int gxf = (bx0 * 2 - 2) * 3;
    const float* xb = x + (size_t)b * (224 * 224 * 3);

    {
        int i  = tid;
        int r  = tid / 54;
        int c2 = tid - r * 54;
#pragma unroll
        for (int it = 0; it < 8; ++it) {
            if (i < 1836) {
                int y    = gy0 + r;
                int fcol = gxf + 2 * c2;
                float2 v = make_float2(0.f, 0.f);
                if ((unsigned)y < 224u && (unsigned)fcol < 672u)
                    v = *(const float2*)(xb + y * 672 + fcol);
                *(float2*)(s + r * 108 + 2 * c2) = v;
            }
            i += 256; r += 4; c2 += 40;
            if (c2 >= 54) { c2 -= 54; r += 1; }
        }
    }
    __syncthreads();

    const int px = tid & 15, py = tid >> 4;
    const u64* cw = (const u64*)c_w1;
    const u64* cb = (const u64*)c_b1;

    u64 acc[2][2][4];
#pragma unroll
    for (int p = 0; p < 4; p++) {
        u64 bp = cb[p];
        acc[0][0][p] = bp; acc[0][1][p] = bp; acc[1][0][p] = bp; acc[1][1][p] = bp;
    }

    const float* tb = s + (2 * py) * 108 + (1 + 2 * px) * 3;

#pragma unroll
    for (int ci = 0; ci < 3; ci++) {
        u64 pv[4][4];
#pragma unroll
        for (int r = 0; r < 4; r++)
#pragma unroll
            for (int k = 0; k < 4; k++)
                pv[r][k] = pack2(tb[r * 108 + k * 3 + ci]);
#pragma unroll
        for (int ky = 0; ky < 3; ky++)
#pragma unroll
        for (int kx = 0; kx < 3; kx++) {
            const int wo = (((ky * 3 + kx) * 3 + ci) * 8) >> 1;
            u64 w0 = cw[wo + 0], w1 = cw[wo + 1], w2 = cw[wo + 2], w3 = cw[wo + 3];
#pragma unroll
            for (int dy = 0; dy < 2; dy++)
#pragma unroll
            for (int dx = 0; dx < 2; dx++) {
                u64 vv = pv[dy + ky][dx + kx];
                ffma2(acc[dy][dx][0], vv, w0);
                ffma2(acc[dy][dx][1], vv, w1);
                ffma2(acc[dy][dx][2], vv, w2);
                ffma2(acc[dy][dx][3], vv, w3);
            }
        }
    }

    float o[8];
#pragma unroll
    for (int p = 0; p < 4; p++) {
        float a0, a1, b0f, b1f, c0, c1, d0, d1;
        unpack2(acc[0][0][p], a0, a1);
        unpack2(acc[0][1][p], b0f, b1f);
        unpack2(acc[1][0][p], c0, c1);
        unpack2(acc[1][1][p], d0, d1);
        o[2 * p]     = fmaxf(fmaxf(fmaxf(a0, b0f), fmaxf(c0, d0)), 0.f);
        o[2 * p + 1] = fmaxf(fmaxf(fmaxf(a1, b1f), fmaxf(c1, d1)), 0.f);
    }
    float* dst = g_p1 + (((size_t)b * 112 + by0 + py) * 112 + (bx0 + px)) * 8;
    *(float4*)dst       = make_float4(o[0], o[1], o[2], o[3]);
    *((float4*)dst + 1) = make_float4(o[4], o[5], o[6], o[7]);
}

// ---------------------------------------------------------------------------
// conv2 + relu + 2x2 maxpool.  Block = 224 thr -> 28x8 pooled tile.
// ---------------------------------------------------------------------------
__global__ void __launch_bounds__(224, 2)
k_conv2() {
    __shared__ float s[8 * 1084];

    const int tid = threadIdx.x;
    const int b   = blockIdx.z;
    const int by0 = blockIdx.y * 8, bx0 = blockIdx.x * 28;
    const int gy0 = by0 * 2 - 1, gx0 = bx0 * 2 - 1;
    const float* pb = g_p1 + (size_t)b * (112 * 112 * 8);

    {
        int i  = tid;
        int r  = tid / 116;
        int c2 = tid - r * 116;
#pragma unroll
        for (int it = 0; it < 10; ++it) {
            if (i < 2088) {
                int col = c2 >> 1, half = c2 & 1;
                int y = gy0 + r, xc = gx0 + col;
                float4 v = make_float4(0.f, 0.f, 0.f, 0.f);
                if ((unsigned)y < 112u && (unsigned)xc < 112u)
                    v = *(const float4*)(pb + ((size_t)(y * 112 + xc)) * 8 + half * 4);
                int base = r * 60 + col;
                int c0 = half * 4;
                s[(c0 + 0) * 1084 + base] = v.x;
                s[(c0 + 1) * 1084 + base] = v.y;
                s[(c0 + 2) * 1084 + base] = v.z;
                s[(c0 + 3) * 1084 + base] = v.w;
            }
            i += 224; r += 1; c2 += 108;
            if (c2 >= 116) { c2 -= 116; r += 1; }
        }
    }
    __syncthreads();

    const int py = tid / 28, px = tid - py * 28;
    const u64* cw = (const u64*)c_w2;
    const u64* cb = (const u64*)c_b2;

    u64 acc[2][2][5];
#pragma unroll
    for (int p = 0; p < 5; p++) {
        u64 bp = cb[p];
        acc[0][0][p] = bp; acc[0][1][p] = bp; acc[1][0][p] = bp; acc[1][1][p] = bp;
    }

#pragma unroll
    for (int ci = 0; ci < 8; ci++) {
        const float* sp = s + ci * 1084 + (2 * py) * 60 + 2 * px;
        u64 pv[4][4];
#pragma unroll
        for (int r = 0; r < 4; r++) {
            float2 a = *(const float2*)(sp + r * 60);
            float2 c = *(const float2*)(sp + r * 60 + 2);
            pv[r][0] = pack2(a.x); pv[r][1] = pack2(a.y);
            pv[r][2] = pack2(c.x); pv[r][3] = pack2(c.y);
        }
#pragma unroll
        for (int ky = 0; ky < 3; ky++)
#pragma unroll
        for (int kx = 0; kx < 3; kx++) {
            const int wo = (((ky * 3 + kx) * 8 + ci) * 10) >> 1;
            u64 w0 = cw[wo + 0], w1 = cw[wo + 1], w2 = cw[wo + 2],
                w3 = cw[wo + 3], w4 = cw[wo + 4];
#pragma unroll
            for (int dy = 0; dy < 2; dy++)
#pragma unroll
            for (int dx = 0; dx < 2; dx++) {
                u64 vv = pv[dy + ky][dx + kx];
                ffma2(acc[dy][dx][0], vv, w0);
                ffma2(acc[dy][dx][1], vv, w1);
                ffma2(acc[dy][dx][2], vv, w2);
                ffma2(acc[dy][dx][3], vv, w3);
                ffma2(acc[dy][dx][4], vv, w4);
            }
        }
    }

    float o[10];
#pragma unroll
    for (int p = 0; p < 5; p++) {
        float a0, a1, b0f, b1f, c0, c1, d0, d1;
        unpack2(acc[0][0][p], a0, a1);
        unpack2(acc[0][1][p], b0f, b1f);
        unpack2(acc[1][0][p], c0, c1);
        unpack2(acc[1][1][p], d0, d1);
        o[2 * p]     = fmaxf(fmaxf(fmaxf(a0, b0f), fmaxf(c0, d0)), 0.f);
        o[2 * p + 1] = fmaxf(fmaxf(fmaxf(a1, b1f), fmaxf(c1, d1)), 0.f);
    }
    float* dst = g_p2 + (((size_t)b * 56 + by0 + py) * 56 + (bx0 + px)) * 10;
#pragma unroll
    for (int p = 0; p < 5; p++)
        *(float2*)(dst + 2 * p) = make_float2(o[2 * p], o[2 * p + 1]);
}

// ---------------------------------------------------------------------------
// fc1 partials: grid (8 k-splits, 32 batch-groups), 256 thr. 4 batches/block.
// ---------------------------------------------------------------------------
__global__ void __launch_bounds__(256)
k_fc1(const float* __restrict__ w) {
    __shared__ float sred[8 * 128];
    const int ks = blockIdx.x, bg = blockIdx.y;
    const int tid = threadIdx.x;
    const int jh = tid & 1;
    const int kl = tid >> 1;

    float acc[4][16];
#pragma unroll
    for (int bb = 0; bb < 4; bb++)
#pragma unroll
        for (int j = 0; j < 16; j++) acc[bb][j] = 0.f;

    const float* p0 = g_p2 + (size_t)(bg * 4 + 0) * 31360;
    const float* p1 = p0 + 31360;
    const float* p2 = p0 + 2 * 31360;
    const float* p3 = p0 + 3 * 31360;
    const int kend = ks * 3920 + 3920;

    for (int k = ks * 3920 + kl; k < kend; k += 128) {
        const float* wr = w + (size_t)k * 32 + jh * 16;
        float4 wa = *(const float4*)(wr);
        float4 wb = *(const float4*)(wr + 4);
        float4 wc = *(const float4*)(wr + 8);
        float4 wd = *(const float4*)(wr + 12);
        float wv[16] = {wa.x, wa.y, wa.z, wa.w, wb.x, wb.y, wb.z, wb.w,
                        wc.x, wc.y, wc.z, wc.w, wd.x, wd.y, wd.z, wd.w};
        float vs[4] = {p0[k], p1[k], p2[k], p3[k]};
#pragma unroll
        for (int bb = 0; bb < 4; bb++)
#pragma unroll
            for (int j = 0; j < 16; j++)
                acc[bb][j] = fmaf(vs[bb], wv[j], acc[bb][j]);
    }

#pragma unroll
    for (int off = 16; off >= 2; off >>= 1)
#pragma unroll
        for (int bb = 0; bb < 4; bb++)
#pragma unroll
            for (int j = 0; j < 16; j++)
                acc[bb][j] += __shfl_down_sync(0xffffffffu, acc[bb][j], off);

    const int lane = tid & 31, wp = tid >> 5;
    if (lane < 2) {
        float* d = &sred[wp * 128 + lane * 64];
#pragma unroll
        for (int bb = 0; bb < 4; bb++)
#pragma unroll
            for (int j = 0; j < 16; j++) d[bb * 16 + j] = acc[bb][j];
    }
    __syncthreads();
    if (tid < 128) {
        float sum = 0.f;
#pragma unroll
        for (int wp2 = 0; wp2 < 8; wp2++) sum += sred[wp2 * 128 + tid];
        int jh2 = tid >> 6, bb = (tid >> 4) & 3, jj = tid & 15;
        g_part2[ks * 4096 + (bg * 4 + bb) * 32 + jh2 * 16 + jj] = sum;
    }
}

// ---------------------------------------------------------------------------
// FUSED sampler: theta recompute + affine grid + bilinear sampling.
// 256 thr, 2 pixels per thread (pix, pix+256) -> 24 independent LDGs in
// flight per thread; grid 98 x 128.
// ---------------------------------------------------------------------------
__global__ void __launch_bounds__(256)
k_sample(const float* __restrict__ x,
         const float* __restrict__ fc1b, const float* __restrict__ fc2w,
         const float* __restrict__ fc2b, float* __restrict__ out) {
    __shared__ float ts[32];
    __shared__ float th[6];
    const int b   = blockIdx.y;
    const int tid = threadIdx.x;

    if (tid < 32) {
        float sum = fc1b[tid];
#pragma unroll
        for (int ks = 0; ks < 8; ks++) sum += g_part2[ks * 4096 + b * 32 + tid];
        ts[tid] = fmaxf(sum, 0.f);
    }
    __syncthreads();
    if (tid < 6) {
        float t = fc2b[tid];
#pragma unroll
        for (int jj = 0; jj < 32; jj++) t = fmaf(ts[jj], fc2w[jj * 6 + tid], t);
        th[tid] = t;
    }
    __syncthreads();

    const float t0 = th[0], t1 = th[1], t2 = th[2],
                t3 = th[3], t4 = th[4], t5 = th[5];
    const float* xb = x + (size_t)b * 150528;
    float* ob = out + (size_t)b * 150528;

    const int base = blockIdx.x * 512 + tid;          // 98*512 = 50176 exact

#pragma unroll
    for (int u = 0; u < 2; u++) {
        const int pix = base + u * 256;
        const int yy = pix / 224;
        const int xx = pix - yy * 224;

        float xt = fmaf((float)xx, 2.f / 223.f, -1.f);
        float yt = fmaf((float)yy, 2.f / 223.f, -1.f);
        float gx = fmaf(t0, xt, fmaf(t1, yt, t2));
        float gy = fmaf(t3, xt, fmaf(t4, yt, t5));
        float xs = (gx + 1.f) * 111.5f;
        float ys = (gy + 1.f) * 111.5f;

        int x0 = min(max((int)floorf(xs), 0), 223);
        int y0 = min(max((int)floorf(ys), 0), 223);
        int x1 = min(x0 + 1, 223);
        int y1 = min(y0 + 1, 223);
        float x0f = (float)x0, x1f = (float)x1, y0f = (float)y0, y1f = (float)y1;
        float wa = (x1f - xs) * (y1f - ys);
        float wb = (x1f - xs) * (ys - y0f);
        float wc = (xs - x0f) * (y1f - ys);
        float wd = (xs - x0f) * (ys - y0f);

        const float* p00 = xb + (y0 * 224 + x0) * 3;
        const float* p01 = xb + (y1 * 224 + x0) * 3;
        const float* p10 = xb + (y0 * 224 + x1) * 3;
        const float* p11 = xb + (y1 * 224 + x1) * 3;
        float* o = ob + pix * 3;
#pragma unroll
        for (int c = 0; c < 3; c++)
            o[c] = wa * p00[c] + wb * p01[c] + wc * p10[c] + wd * p11[c];
    }
}

// ---------------------------------------------------------------------------
extern "C" void kernel_launch(void* const* d_in, const int* in_sizes, int n_in,
                              void* d_out, int out_size) {
    const float* x   = (const float*)d_in[0];
    const float* c1w = (const float*)d_in[1];
    const float* c1b = (const float*)d_in[2];
    const float* c2w = (const float*)d_in[3];
    const float* c2b = (const float*)d_in[4];
    const float* f1w = (const float*)d_in[5];
    const float* f1b = (const float*)d_in[6];
    const float* f2w = (const float*)d_in[7];
    const float* f2b = (const float*)d_in[8];
    float* out = (float*)d_out;

    cudaMemcpyToSymbolAsync(c_w1, c1w, 216 * sizeof(float), 0,
                            cudaMemcpyDeviceToDevice, 0);
    cudaMemcpyToSymbolAsync(c_b1, c1b, 8 * sizeof(float), 0,
                            cudaMemcpyDeviceToDevice, 0);
    cudaMemcpyToSymbolAsync(c_w2, c2w, 720 * sizeof(float), 0,
                            cudaMemcpyDeviceToDevice, 0);
    cudaMemcpyToSymbolAsync(c_b2, c2b, 10 * sizeof(float), 0,
                            cudaMemcpyDeviceToDevice, 0);

    k_conv1 <<<dim3(7, 7, 128), 256>>> (x);
    k_conv2 <<<dim3(2, 7, 128), 224>>> ();
    k_fc1   <<<dim3(8, 32),     256>>> (f1w);
    // 4th kernel launch (ncu slot): fused theta + 2-px/thread sampler
    k_sample<<<dim3(98, 128),   256>>> (x, f1b, f2w, f2b, out);
}

// round 14
// speedup vs baseline: 1.6650x; 1.0383x over previous
#include <cuda_runtime.h>

// ---------------------------------------------------------------------------
// STN forward: conv1(3->8)+relu+pool -> conv2(8->10)+relu+pool -> fc1(31360->32)
//              +relu -> fc2(32->6)=theta -> affine grid + bilinear sample.
// All fp32. Convs: packed fma.rn.f32x2, weights in __constant__ (R8-proven).
// R14: sampler 4 pixels/thread (MLP 24 -> 48), extending R13's verified win.
// ---------------------------------------------------------------------------

typedef unsigned long long u64;

__device__ __forceinline__ u64 pack2(float v) {
    u64 r; asm("mov.b64 %0, {%1, %1};" : "=l"(r) : "f"(v)); return r;
}
__device__ __forceinline__ void unpack2(u64 v, float& lo, float& hi) {
    asm("mov.b64 {%0, %1}, %2;" : "=f"(lo), "=f"(hi) : "l"(v));
}
__device__ __forceinline__ void ffma2(u64& acc, u64 a, u64 b) {
    asm("fma.rn.f32x2 %0, %1, %2, %0;" : "+l"(acc) : "l"(a), "l"(b));
}

// ------------------------------- weights in constant -----------------------
__constant__ __align__(16) float c_w1[216];   // (3,3,3,8) HWIO
__constant__ __align__(16) float c_b1[8];
__constant__ __align__(16) float c_w2[720];   // (3,3,8,10)
__constant__ __align__(16) float c_b2[10];

// ------------------------------- scratch ----------------------------------
__device__ __align__(16) float g_p1[128 * 112 * 112 * 8];   // pooled conv1 out
__device__ __align__(16) float g_p2[128 * 56 * 56 * 10];    // pooled conv2 out
__device__ float g_part2[8 * 128 * 32];                     // fc1 k-split partials

// ---------------------------------------------------------------------------
// conv1 + relu + 2x2 maxpool.  Block = 256 thr -> 16x16 pooled tile.
// ---------------------------------------------------------------------------
__global__ void __launch_bounds__(256, 4)
k_conv1(const float* __restrict__ x) {
    __shared__ float s[34 * 108];

    const int tid = threadIdx.x;
    const int b   = blockIdx.z;
    const int by0 = blockIdx.y * 16, bx0 = blockIdx.x * 16;
    const int gy0 = by0 * 2 - 1;
    const int gxf = (bx0 * 2 - 2) * 3;
    const float* xb = x + (size_t)b * (224 * 224 * 3);

    {
        int i  = tid;
        int r  = tid / 54;
        int c2 = tid - r * 54;
#pragma unroll
        for (int it = 0; it < 8; ++it) {
            if (i < 1836) {
                int y    = gy0 + r;
                int fcol = gxf + 2 * c2;
                float2 v = make_float2(0.f, 0.f);
                if ((unsigned)y < 224u && (unsigned)fcol < 672u)
                    v = *(const float2*)(xb + y * 672 + fcol);
                *(float2*)(s + r * 108 + 2 * c2) = v;
            }
            i += 256; r += 4; c2 += 40;
            if (c2 >= 54) { c2 -= 54; r += 1; }
        }
    }
    __syncthreads();

    const int px = tid & 15, py = tid >> 4;
    const u64* cw = (const u64*)c_w1;
    const u64* cb = (const u64*)c_b1;

    u64 acc[2][2][4];
#pragma unroll
    for (int p = 0; p < 4; p++) {
        u64 bp = cb[p];
        acc[0][0][p] = bp; acc[0][1][p] = bp; acc[1][0][p] = bp; acc[1][1][p] = bp;
    }

    const float* tb = s + (2 * py) * 108 + (1 + 2 * px) * 3;

#pragma unroll
    for (int ci = 0; ci < 3; ci++) {
        u64 pv[4][4];
#pragma unroll
        for (int r = 0; r < 4; r++)
#pragma unroll
            for (int k = 0; k < 4; k++)
                pv[r][k] = pack2(tb[r * 108 + k * 3 + ci]);
#pragma unroll
        for (int ky = 0; ky < 3; ky++)
#pragma unroll
        for (int kx = 0; kx < 3; kx++) {
            const int wo = (((ky * 3 + kx) * 3 + ci) * 8) >> 1;
            u64 w0 = cw[wo + 0], w1 = cw[wo + 1], w2 = cw[wo + 2], w3 = cw[wo + 3];
#pragma unroll
            for (int dy = 0; dy < 2; dy++)
#pragma unroll
            for (int dx = 0; dx < 2; dx++) {
                u64 vv = pv[dy + ky][dx + kx];
                ffma2(acc[dy][dx][0], vv, w0);
                ffma2(acc[dy][dx][1], vv, w1);
                ffma2(acc[dy][dx][2], vv, w2);
                ffma2(acc[dy][dx][3], vv, w3);
            }
        }
    }

    float o[8];
#pragma unroll
    for (int p = 0; p < 4; p++) {
        float a0, a1, b0f, b1f, c0, c1, d0, d1;
        unpack2(acc[0][0][p], a0, a1);
        unpack2(acc[0][1][p], b0f, b1f);
        unpack2(acc[1][0][p], c0, c1);
        unpack2(acc[1][1][p], d0, d1);
        o[2 * p]     = fmaxf(fmaxf(fmaxf(a0, b0f), fmaxf(c0, d0)), 0.f);
        o[2 * p + 1] = fmaxf(fmaxf(fmaxf(a1, b1f), fmaxf(c1, d1)), 0.f);
    }
    float* dst = g_p1 + (((size_t)b * 112 + by0 + py) * 112 + (bx0 + px)) * 8;
    *(float4*)dst       = make_float4(o[0], o[1], o[2], o[3]);
    *((float4*)dst + 1) = make_float4(o[4], o[5], o[6], o[7]);
}

// ---------------------------------------------------------------------------
// conv2 + relu + 2x2 maxpool.  Block = 224 thr -> 28x8 pooled tile.
// ---------------------------------------------------------------------------
__global__ void __launch_bounds__(224, 2)
k_conv2() {
    __shared__ float s[8 * 1084];

    const int tid = threadIdx.x;
    const int b   = blockIdx.z;
    const int by0 = blockIdx.y * 8, bx0 = blockIdx.x * 28;
    const int gy0 = by0 * 2 - 1, gx0 = bx0 * 2 - 1;
    const float* pb = g_p1 + (size_t)b * (112 * 112 * 8);

    {
        int i  = tid;
        int r  = tid / 116;
        int c2 = tid - r * 116;
#pragma unroll
        for (int it = 0; it < 10; ++it) {
            if (i < 2088) {
                int col = c2 >> 1, half = c2 & 1;
                int y = gy0 + r, xc = gx0 + col;
                float4 v = make_float4(0.f, 0.f, 0.f, 0.f);
                if ((unsigned)y < 112u && (unsigned)xc < 112u)
                    v = *(const float4*)(pb + ((size_t)(y * 112 + xc)) * 8 + half * 4);
                int base = r * 60 + col;
                int c0 = half * 4;
                s[(c0 + 0) * 1084 + base] = v.x;
                s[(c0 + 1) * 1084 + base] = v.y;
                s[(c0 + 2) * 1084 + base] = v.z;
                s[(c0 + 3) * 1084 + base] = v.w;
            }
            i += 224; r += 1; c2 += 108;
            if (c2 >= 116) { c2 -= 116; r += 1; }
        }
    }
    __syncthreads();

    const int py = tid / 28, px = tid - py * 28;
    const u64* cw = (const u64*)c_w2;
    const u64* cb = (const u64*)c_b2;

    u64 acc[2][2][5];
#pragma unroll
    for (int p = 0; p < 5; p++) {
        u64 bp = cb[p];
        acc[0][0][p] = bp; acc[0][1][p] = bp; acc[1][0][p] = bp; acc[1][1][p] = bp;
    }

#pragma unroll
    for (int ci = 0; ci < 8; ci++) {
        const float* sp = s + ci * 1084 + (2 * py) * 60 + 2 * px;
        u64 pv[4][4];
#pragma unroll
        for (int r = 0; r < 4; r++) {
            float2 a = *(const float2*)(sp + r * 60);
            float2 c = *(const float2*)(sp + r * 60 + 2);
            pv[r][0] = pack2(a.x); pv[r][1] = pack2(a.y);
            pv[r][2] = pack2(c.x); pv[r][3] = pack2(c.y);
        }
#pragma unroll
        for (int ky = 0; ky < 3; ky++)
#pragma unroll
        for (int kx = 0; kx < 3; kx++) {
            const int wo = (((ky * 3 + kx) * 8 + ci) * 10) >> 1;
            u64 w0 = cw[wo + 0], w1 = cw[wo + 1], w2 = cw[wo + 2],
                w3 = cw[wo + 3], w4 = cw[wo + 4];
#pragma unroll
            for (int dy = 0; dy < 2; dy++)
#pragma unroll
            for (int dx = 0; dx < 2; dx++) {
                u64 vv = pv[dy + ky][dx + kx];
                ffma2(acc[dy][dx][0], vv, w0);
                ffma2(acc[dy][dx][1], vv, w1);
                ffma2(acc[dy][dx][2], vv, w2);
                ffma2(acc[dy][dx][3], vv, w3);
                ffma2(acc[dy][dx][4], vv, w4);
            }
        }
    }

    float o[10];
#pragma unroll
    for (int p = 0; p < 5; p++) {
        float a0, a1, b0f, b1f, c0, c1, d0, d1;
        unpack2(acc[0][0][p], a0, a1);
        unpack2(acc[0][1][p], b0f, b1f);
        unpack2(acc[1][0][p], c0, c1);
        unpack2(acc[1][1][p], d0, d1);
        o[2 * p]     = fmaxf(fmaxf(fmaxf(a0, b0f), fmaxf(c0, d0)), 0.f);
        o[2 * p + 1] = fmaxf(fmaxf(fmaxf(a1, b1f), fmaxf(c1, d1)), 0.f);
    }
    float* dst = g_p2 + (((size_t)b * 56 + by0 + py) * 56 + (bx0 + px)) * 10;
#pragma unroll
    for (int p = 0; p < 5; p++)
        *(float2*)(dst + 2 * p) = make_float2(o[2 * p], o[2 * p + 1]);
}

// ---------------------------------------------------------------------------
// fc1 partials: grid (8 k-splits, 32 batch-groups), 256 thr. 4 batches/block.
// ---------------------------------------------------------------------------
__global__ void __launch_bounds__(256)
k_fc1(const float* __restrict__ w) {
    __shared__ float sred[8 * 128];
    const int ks = blockIdx.x, bg = blockIdx.y;
    const int tid = threadIdx.x;
    const int jh = tid & 1;
    const int kl = tid >> 1;

    float acc[4][16];
#pragma unroll
    for (int bb = 0; bb < 4; bb++)
#pragma unroll
        for (int j = 0; j < 16; j++) acc[bb][j] = 0.f;

    const float* p0 = g_p2 + (size_t)(bg * 4 + 0) * 31360;
    const float* p1 = p0 + 31360;
    const float* p2 = p0 + 2 * 31360;
    const float* p3 = p0 + 3 * 31360;
    const int kend = ks * 3920 + 3920;

    for (int k = ks * 3920 + kl; k < kend; k += 128) {
        const float* wr = w + (size_t)k * 32 + jh * 16;
        float4 wa = *(const float4*)(wr);
        float4 wb = *(const float4*)(wr + 4);
        float4 wc = *(const float4*)(wr + 8);
        float4 wd = *(const float4*)(wr + 12);
        float wv[16] = {wa.x, wa.y, wa.z, wa.w, wb.x, wb.y, wb.z, wb.w,
                        wc.x, wc.y, wc.z, wc.w, wd.x, wd.y, wd.z, wd.w};
        float vs[4] = {p0[k], p1[k], p2[k], p3[k]};
#pragma unroll
        for (int bb = 0; bb < 4; bb++)
#pragma unroll
            for (int j = 0; j < 16; j++)
                acc[bb][j] = fmaf(vs[bb], wv[j], acc[bb][j]);
    }

#pragma unroll
    for (int off = 16; off >= 2; off >>= 1)
#pragma unroll
        for (int bb = 0; bb < 4; bb++)
#pragma unroll
            for (int j = 0; j < 16; j++)
                acc[bb][j] += __shfl_down_sync(0xffffffffu, acc[bb][j], off);

    const int lane = tid & 31, wp = tid >> 5;
    if (lane < 2) {
        float* d = &sred[wp * 128 + lane * 64];
#pragma unroll
        for (int bb = 0; bb < 4; bb++)
#pragma unroll
            for (int j = 0; j < 16; j++) d[bb * 16 + j] = acc[bb][j];
    }
    __syncthreads();
    if (tid < 128) {
        float sum = 0.f;
#pragma unroll
        for (int wp2 = 0; wp2 < 8; wp2++) sum += sred[wp2 * 128 + tid];
        int jh2 = tid >> 6, bb = (tid >> 4) & 3, jj = tid & 15;
        g_part2[ks * 4096 + (bg * 4 + bb) * 32 + jh2 * 16 + jj] = sum;
    }
}

// ---------------------------------------------------------------------------
// FUSED sampler: theta recompute + affine grid + bilinear sampling.
// 256 thr, 4 pixels per thread (pix + u*256) -> ~48 independent LDGs in
// flight per thread; grid 49 x 128.
// ---------------------------------------------------------------------------
__global__ void __launch_bounds__(256)
k_sample(const float* __restrict__ x,
         const float* __restrict__ fc1b, const float* __restrict__ fc2w,
         const float* __restrict__ fc2b, float* __restrict__ out) {
    __shared__ float ts[32];
    __shared__ float th[6];
    const int b   = blockIdx.y;
    const int tid = threadIdx.x;

    if (tid < 32) {
        float sum = fc1b[tid];
#pragma unroll
        for (int ks = 0; ks < 8; ks++) sum += g_part2[ks * 4096 + b * 32 + tid];
        ts[tid] = fmaxf(sum, 0.f);
    }
    __syncthreads();
    if (tid < 6) {
        float t = fc2b[tid];
#pragma unroll
        for (int jj = 0; jj < 32; jj++) t = fmaf(ts[jj], fc2w[jj * 6 + tid], t);
        th[tid] = t;
    }
    __syncthreads();

    const float t0 = th[0], t1 = th[1], t2 = th[2],
                t3 = th[3], t4 = th[4], t5 = th[5];
    const float* xb = x + (size_t)b * 150528;
    float* ob = out + (size_t)b * 150528;

    const int base = blockIdx.x * 1024 + tid;         // 49*1024 = 50176 exact

#pragma unroll
    for (int u = 0; u < 4; u++) {
        const int pix = base + u * 256;
        const int yy = pix / 224;
        const int xx = pix - yy * 224;

        float xt = fmaf((float)xx, 2.f / 223.f, -1.f);
        float yt = fmaf((float)yy, 2.f / 223.f, -1.f);
        float gx = fmaf(t0, xt, fmaf(t1, yt, t2));
        float gy = fmaf(t3, xt, fmaf(t4, yt, t5));
        float xs = (gx + 1.f) * 111.5f;
        float ys = (gy + 1.f) * 111.5f;

        int x0 = min(max((int)floorf(xs), 0), 223);
        int y0 = min(max((int)floorf(ys), 0), 223);
        int x1 = min(x0 + 1, 223);
        int y1 = min(y0 + 1, 223);
        float x0f = (float)x0, x1f = (float)x1, y0f = (float)y0, y1f = (float)y1;
        float wa = (x1f - xs) * (y1f - ys);
        float wb = (x1f - xs) * (ys - y0f);
        float wc = (xs - x0f) * (y1f - ys);
        float wd = (xs - x0f) * (ys - y0f);

        const float* p00 = xb + (y0 * 224 + x0) * 3;
        const float* p01 = xb + (y1 * 224 + x0) * 3;
        const float* p10 = xb + (y0 * 224 + x1) * 3;
        const float* p11 = xb + (y1 * 224 + x1) * 3;
        float* o = ob + pix * 3;
#pragma unroll
        for (int c = 0; c < 3; c++)
            o[c] = wa * p00[c] + wb * p01[c] + wc * p10[c] + wd * p11[c];
    }
}

// ---------------------------------------------------------------------------
extern "C" void kernel_launch(void* const* d_in, const int* in_sizes, int n_in,
                              void* d_out, int out_size) {
    const float* x   = (const float*)d_in[0];
    const float* c1w = (const float*)d_in[1];
    const float* c1b = (const float*)d_in[2];
    const float* c2w = (const float*)d_in[3];
    const float* c2b = (const float*)d_in[4];
    const float* f1w = (const float*)d_in[5];
    const float* f1b = (const float*)d_in[6];
    const float* f2w = (const float*)d_in[7];
    const float* f2b = (const float*)d_in[8];
    float* out = (float*)d_out;

    cudaMemcpyToSymbolAsync(c_w1, c1w, 216 * sizeof(float), 0,
                            cudaMemcpyDeviceToDevice, 0);
    cudaMemcpyToSymbolAsync(c_b1, c1b, 8 * sizeof(float), 0,
                            cudaMemcpyDeviceToDevice, 0);
    cudaMemcpyToSymbolAsync(c_w2, c2w, 720 * sizeof(float), 0,
                            cudaMemcpyDeviceToDevice, 0);
    cudaMemcpyToSymbolAsync(c_b2, c2b, 10 * sizeof(float), 0,
                            cudaMemcpyDeviceToDevice, 0);

    k_conv1 <<<dim3(7, 7, 128), 256>>> (x);
    k_conv2 <<<dim3(2, 7, 128), 224>>> ();
    k_fc1   <<<dim3(8, 32),     256>>> (f1w);
    // 4th kernel launch (ncu slot): fused theta + 4-px/thread sampler
    k_sample<<<dim3(49, 128),   256>>> (x, f1b, f2w, f2b, out);
}